// round 16
// baseline (speedup 1.0000x reference)
#include <cuda_runtime.h>
#include <math.h>
#include <stdint.h>

#define T_LEN  2048
#define IN_DIM 1024
#define H_DIM  1024
#define FH     4096
#define C_DIM  1000
#define NCTA_DIR 64
#define SCAN_SMEM (17*1024*4 + 128)

// ---------------- device scratch (no allocations allowed) ----------------
__device__ __align__(16) float g_xp[2][T_LEN][FH];      // input projections (fwd, bwd-reversed order)
__device__ __align__(16) float g_hs[2][T_LEN][H_DIM];   // all hidden states (bwd stored in reversed time)
__device__ __align__(16) float g_hbuf[2][2][H_DIM];     // double-buffered h per direction
// per-CTA progress flags, padded to 256B so consecutive flags land on distinct LTS slices
__device__ __align__(256) unsigned g_flag[2][NCTA_DIR][64];

__device__ __forceinline__ void st_release_u32(unsigned* p, unsigned v) {
    asm volatile("st.release.gpu.global.u32 [%0],%1;" :: "l"(p), "r"(v) : "memory");
}
__device__ __forceinline__ unsigned ld_acquire_u32(const unsigned* p) {
    unsigned v;
    asm volatile("ld.acquire.gpu.global.u32 %0,[%1];" : "=r"(v) : "l"(p) : "memory");
    return v;
}
__device__ __forceinline__ uint32_t smem_u32(const void* p) {
    uint32_t a;
    asm("{ .reg .u64 t; cvta.to.shared.u64 t, %1; cvt.u32.u64 %0, t; }" : "=r"(a) : "l"(p));
    return a;
}
__device__ __forceinline__ void st_release_shared(uint32_t a, unsigned v) {
    asm volatile("st.release.cta.shared.u32 [%0],%1;" :: "r"(a), "r"(v) : "memory");
}
__device__ __forceinline__ unsigned ld_acquire_shared(uint32_t a) {
    unsigned v;
    asm volatile("ld.acquire.cta.shared.u32 %0,[%1];" : "=r"(v) : "r"(a) : "memory");
    return v;
}

// packed dual-FMA: one instruction, two exact fp32 FMAs (sm_103a FFMA2)
__device__ __forceinline__ void fma2(unsigned long long& acc,
                                     unsigned long long a, unsigned long long b) {
    asm("fma.rn.f32x2 %0, %1, %2, %0;" : "+l"(acc) : "l"(a), "l"(b));
}
__device__ __forceinline__ float f32x2_sum(unsigned long long p) {
    unsigned lo, hi;
    asm("mov.b64 {%0,%1}, %2;" : "=r"(lo), "=r"(hi) : "l"(p));
    return __uint_as_float(lo) + __uint_as_float(hi);
}

__device__ __forceinline__ float to_tf32(float x) {
    uint32_t u;
    asm("cvt.rna.tf32.f32 %0, %1;" : "=r"(u) : "f"(x));
    return __uint_as_float(u);
}

__device__ __forceinline__ void mma_tf32(float* c, const uint32_t* a, const uint32_t* b) {
    asm volatile(
        "mma.sync.aligned.m16n8k8.row.col.f32.tf32.tf32.f32 "
        "{%0,%1,%2,%3}, {%4,%5,%6,%7}, {%8,%9}, {%0,%1,%2,%3};\n"
        : "+f"(c[0]), "+f"(c[1]), "+f"(c[2]), "+f"(c[3])
        : "r"(a[0]), "r"(a[1]), "r"(a[2]), "r"(a[3]), "r"(b[0]), "r"(b[1]));
}

__device__ __forceinline__ int swz(int r, int c) {
    return r * 32 + ((((c >> 2) ^ (r & 7)) << 2) | (c & 3));
}

// ---------------- init: reset flags + h0 every launch/replay ----------------
__global__ void init_kernel() {
    int tid = blockIdx.x * blockDim.x + threadIdx.x;
    if (tid < 2 * 2 * H_DIM) ((float*)g_hbuf)[tid] = 0.f;
    if (tid < 2 * NCTA_DIR * 64) ((unsigned*)g_flag)[tid] = 1u;   // h[0] ready
}

// ---------------- phase 1: x @ W_ih^T + b_ih + b_hh via TF32 tensor cores ----------------
__global__ __launch_bounds__(256, 1) void xproj_mma(
    const float* __restrict__ x,
    const float* __restrict__ Wf, const float* __restrict__ Wb,
    const float* __restrict__ bif, const float* __restrict__ bhf,
    const float* __restrict__ bib, const float* __restrict__ bhb)
{
    const int dir = blockIdx.z;
    const float* __restrict__ W  = dir ? Wb  : Wf;
    const float* __restrict__ b1 = dir ? bib : bif;
    const float* __restrict__ b2 = dir ? bhb : bhf;

    __shared__ float sA[128 * 32];
    __shared__ float sB[128 * 32];

    const int tid = threadIdx.x;
    const int warp = tid >> 5, l = tid & 31;
    const int wm = warp >> 1, wn = warp & 1;
    const int g = l >> 2, t = l & 3;
    const int m0 = blockIdx.y * 128, n0 = blockIdx.x * 128;

    const int sr  = tid >> 3;
    const int sc4 = tid & 7;
    const int scs = ((sc4 ^ (sr & 7)) << 2);

    float acc[2][8][4];
    #pragma unroll
    for (int mi = 0; mi < 2; ++mi)
        #pragma unroll
        for (int ni = 0; ni < 8; ++ni)
            #pragma unroll
            for (int e = 0; e < 4; ++e) acc[mi][ni][e] = 0.f;

    float4 pa[4], pb[4];
    {
        const int kc = sc4 * 4;
        #pragma unroll
        for (int p = 0; p < 4; ++p) {
            int m = m0 + sr + 32 * p;
            int ar = dir ? (T_LEN - 1 - m) : m;
            pa[p] = *(const float4*)(x + (size_t)ar * IN_DIM + kc);
            pb[p] = *(const float4*)(W + (size_t)(n0 + sr + 32 * p) * IN_DIM + kc);
        }
        #pragma unroll
        for (int p = 0; p < 4; ++p) {
            int r = sr + 32 * p;
            float* da = &sA[r * 32 + scs];
            float* db = &sB[r * 32 + scs];
            da[0] = to_tf32(pa[p].x); da[1] = to_tf32(pa[p].y); da[2] = to_tf32(pa[p].z); da[3] = to_tf32(pa[p].w);
            db[0] = to_tf32(pb[p].x); db[1] = to_tf32(pb[p].y); db[2] = to_tf32(pb[p].z); db[3] = to_tf32(pb[p].w);
        }
    }
    __syncthreads();

    for (int kt = 0; kt < IN_DIM / 32; ++kt) {
        if (kt < IN_DIM / 32 - 1) {
            const int kc = (kt + 1) * 32 + sc4 * 4;
            #pragma unroll
            for (int p = 0; p < 4; ++p) {
                int m = m0 + sr + 32 * p;
                int ar = dir ? (T_LEN - 1 - m) : m;
                pa[p] = *(const float4*)(x + (size_t)ar * IN_DIM + kc);
                pb[p] = *(const float4*)(W + (size_t)(n0 + sr + 32 * p) * IN_DIM + kc);
            }
        }
        #pragma unroll
        for (int k8 = 0; k8 < 4; ++k8) {
            const int kk = k8 * 8;
            uint32_t a[2][4], b[8][2];
            #pragma unroll
            for (int mi = 0; mi < 2; ++mi) {
                int r = wm * 32 + mi * 16 + g;
                a[mi][0] = __float_as_uint(sA[swz(r,     kk + t)]);
                a[mi][1] = __float_as_uint(sA[swz(r + 8, kk + t)]);
                a[mi][2] = __float_as_uint(sA[swz(r,     kk + t + 4)]);
                a[mi][3] = __float_as_uint(sA[swz(r + 8, kk + t + 4)]);
            }
            #pragma unroll
            for (int ni = 0; ni < 8; ++ni) {
                int rn = wn * 64 + ni * 8 + g;
                b[ni][0] = __float_as_uint(sB[swz(rn, kk + t)]);
                b[ni][1] = __float_as_uint(sB[swz(rn, kk + t + 4)]);
            }
            #pragma unroll
            for (int mi = 0; mi < 2; ++mi)
                #pragma unroll
                for (int ni = 0; ni < 8; ++ni)
                    mma_tf32(acc[mi][ni], a[mi], b[ni]);
        }
        __syncthreads();
        if (kt < IN_DIM / 32 - 1) {
            #pragma unroll
            for (int p = 0; p < 4; ++p) {
                int r = sr + 32 * p;
                float* da = &sA[r * 32 + scs];
                float* db = &sB[r * 32 + scs];
                da[0] = to_tf32(pa[p].x); da[1] = to_tf32(pa[p].y); da[2] = to_tf32(pa[p].z); da[3] = to_tf32(pa[p].w);
                db[0] = to_tf32(pb[p].x); db[1] = to_tf32(pb[p].y); db[2] = to_tf32(pb[p].z); db[3] = to_tf32(pb[p].w);
            }
            __syncthreads();
        }
    }

    #pragma unroll
    for (int mi = 0; mi < 2; ++mi) {
        int r0 = m0 + wm * 32 + mi * 16 + g;
        #pragma unroll
        for (int ni = 0; ni < 8; ++ni) {
            int n = n0 + wn * 64 + ni * 8 + 2 * t;
            float bb0 = __ldg(b1 + n)     + __ldg(b2 + n);
            float bb1 = __ldg(b1 + n + 1) + __ldg(b2 + n + 1);
            float2 v0 = make_float2(acc[mi][ni][0] + bb0, acc[mi][ni][1] + bb1);
            float2 v1 = make_float2(acc[mi][ni][2] + bb0, acc[mi][ni][3] + bb1);
            *(float2*)&g_xp[dir][r0][n]     = v0;
            *(float2*)&g_xp[dir][r0 + 8][n] = v1;
        }
    }
}

// ---------------- phase 2: persistent LSTM scan, chunked dataflow staging ----------------
// 128 CTAs (blockIdx>>6 = direction, &63 = chunk). 256 threads = 8 warps, 2 units/warp.
// Unit A: all 4 gates regs. Unit B: gates 0,1 regs; gates 2,3 smem. FFMA2 GEMV.
// NEW: warp w stages ONLY h-chunk w (128 floats from producer CTAs 8w..8w+7): lane l
// acquire-polls flag[8w+(l>>2)] (its own producer) then __ldcg + STS, and publishes
// chunk readiness via a monotonic smem counter (st.release.cta). The GEMV gates each
// jj-block on its chunk counter -> a straggler producer overlaps with up to 7 chunks
// of FMA work instead of blocking the whole step.
__global__ __launch_bounds__(256, 1) void scan_kernel(
    const float* __restrict__ Whh_f, const float* __restrict__ Whh_b)
{
    extern __shared__ float smem[];
    float* sW = smem;                       // 16 rows x 1024: unit B gates {2,3}
    float* sH = smem + 16*1024;             // 1024 (staged h)
    unsigned* scnt = (unsigned*)(smem + 17*1024);   // 8 chunk counters (monotonic)

    const int dir = blockIdx.x >> 6;
    const int cb  = blockIdx.x & 63;
    const float* __restrict__ Whh = dir ? Whh_b : Whh_f;

    const int tid = threadIdx.x;
    const int w = tid >> 5;
    const int l = tid & 31;
    const int uA = cb*16 + w;        // register unit (all 4 gates)
    const int uB = cb*16 + 8 + w;    // mixed unit (gates 0,1 regs; 2,3 smem)

    // cooperative load of smem weights: unit B gates {2,3}, 16 rows
    for (int i = tid; i < 16 * 256; i += 256) {
        int rr   = i >> 8;        // 0..15
        int col4 = i & 255;
        int lw   = rr >> 1;
        int gate = 2 + (rr & 1);
        int uu   = cb*16 + 8 + lw;
        ((float4*)sW)[i] = __ldg((const float4*)(Whh + (size_t)(gate*H_DIM + uu)*H_DIM) + col4);
    }

    // register weights as packed f32x2 pairs: unit A gates 0..3, unit B gates 0..1
    ulonglong2 wrA[4][8];
    #pragma unroll
    for (int g = 0; g < 4; ++g) {
        const ulonglong2* base = (const ulonglong2*)(Whh + (size_t)(g*H_DIM + uA)*H_DIM);
        #pragma unroll
        for (int jj = 0; jj < 8; ++jj)
            wrA[g][jj] = __ldg(base + (l + 32*jj));
    }
    ulonglong2 wrB[2][8];
    #pragma unroll
    for (int g = 0; g < 2; ++g) {
        const ulonglong2* base = (const ulonglong2*)(Whh + (size_t)(g*H_DIM + uB)*H_DIM);
        #pragma unroll
        for (int jj = 0; jj < 8; ++jj)
            wrB[g][jj] = __ldg(base + (l + 32*jj));
    }
    if (tid < 8) scnt[tid] = 0u;
    __syncthreads();

    float c = 0.f;                               // lanes<16: cA; lanes>=16: cB
    const float* xp = &g_xp[dir][0][0];
    float* hs = &g_hs[dir][0][0];
    const int xrow = (((l >> 2) & 3))*H_DIM + ((l & 16) ? uB : uA);
    const unsigned* myflag = &g_flag[dir][8*w + (l >> 2)][0];   // producer of this lane's staged float4
    const uint32_t scnt_base = smem_u32(scnt);
    const uint32_t my_scnt   = scnt_base + 4u*(unsigned)w;
    const int bsel = l & 16;                     // shfl source base: 0 (unit A) / 16 (unit B)

    for (int step = 0; step < T_LEN; ++step) {
        // independent gmem load issued early to overlap with polling
        float xpv = __ldg(xp + (size_t)step*FH + xrow);

        const unsigned expect = (unsigned)(step + 1);

        // stage chunk w: poll own producer's flag, fetch own float4, STS, publish counter
        for (;;) {
            unsigned f = ld_acquire_u32(myflag);
            if (__all_sync(0xffffffffu, f >= expect)) break;
        }
        {
            const float4* hp = (const float4*)&g_hbuf[dir][step & 1][0] + (32*w + l);
            ((float4*)sH)[32*w + l] = __ldcg(hp);
        }
        __threadfence_block();
        __syncwarp();
        if (l == 0) st_release_shared(my_scnt, expect);

        unsigned long long acc2[8];
        #pragma unroll
        for (int g = 0; g < 8; ++g) acc2[g] = 0ull;   // packed {0.f, 0.f}

        const ulonglong2* sH2 = (const ulonglong2*)sH;
        const ulonglong2* sW2 = (const ulonglong2*)sW;
        const ulonglong2* r6 = sW2 + (w*2 + 0)*256;   // unit B gate 2
        const ulonglong2* r7 = sW2 + (w*2 + 1)*256;   // unit B gate 3
        #pragma unroll
        for (int jj = 0; jj < 8; ++jj) {
            // gate this chunk's FMAs on its stager's counter (cheap LDS-broadcast spin)
            while (ld_acquire_shared(scnt_base + 4u*jj) < expect) { }
            ulonglong2 hq = sH2[l + 32*jj];
            #pragma unroll
            for (int g = 0; g < 4; ++g) {
                fma2(acc2[g], wrA[g][jj].x, hq.x);
                fma2(acc2[g], wrA[g][jj].y, hq.y);
            }
            fma2(acc2[4], wrB[0][jj].x, hq.x);
            fma2(acc2[4], wrB[0][jj].y, hq.y);
            fma2(acc2[5], wrB[1][jj].x, hq.x);
            fma2(acc2[5], wrB[1][jj].y, hq.y);
            ulonglong2 q2 = r6[l + 32*jj];
            ulonglong2 q3 = r7[l + 32*jj];
            fma2(acc2[6], q2.x, hq.x);
            fma2(acc2[6], q2.y, hq.y);
            fma2(acc2[7], q3.x, hq.x);
            fma2(acc2[7], q3.y, hq.y);
        }
        float acc[8];
        #pragma unroll
        for (int g = 0; g < 8; ++g) acc[g] = f32x2_sum(acc2[g]);

        // value-merging butterfly: 16 shfls
        #pragma unroll
        for (int g = 0; g < 8; ++g) acc[g] += __shfl_xor_sync(0xffffffffu, acc[g], 16);
        float v0 = (l & 16) ? acc[4] : acc[0];
        float v1 = (l & 16) ? acc[5] : acc[1];
        float v2 = (l & 16) ? acc[6] : acc[2];
        float v3 = (l & 16) ? acc[7] : acc[3];
        v0 += __shfl_xor_sync(0xffffffffu, v0, 8);
        v1 += __shfl_xor_sync(0xffffffffu, v1, 8);
        v2 += __shfl_xor_sync(0xffffffffu, v2, 8);
        v3 += __shfl_xor_sync(0xffffffffu, v3, 8);
        float u0 = (l & 8) ? v2 : v0;
        float u1 = (l & 8) ? v3 : v1;
        u0 += __shfl_xor_sync(0xffffffffu, u0, 4);
        u1 += __shfl_xor_sync(0xffffffffu, u1, 4);
        float t = (l & 4) ? u1 : u0;
        t += __shfl_xor_sync(0xffffffffu, t, 2);
        t += __shfl_xor_sync(0xffffffffu, t, 1);
        // lane l holds gate sum for g(l) = 4*(l>>4) + ((l>>2)&3)

        float pre = t + xpv;
        float act;
        if (((l >> 2) & 3) == 2) {             // candidate gate: tanh
            float e = __expf(-2.f * fabsf(pre));
            act = copysignf(__fdividef(1.f - e, 1.f + e), pre);
        } else {                               // i/f/o gates: sigmoid
            act = __fdividef(1.f, 1.f + __expf(-pre));
        }

        // 4 broadcasts: lanes<16 gather unit A's gates, lanes>=16 unit B's
        float iv = __shfl_sync(0xffffffffu, act, bsel + 0);
        float fv = __shfl_sync(0xffffffffu, act, bsel + 4);
        float gv = __shfl_sync(0xffffffffu, act, bsel + 8);
        float ov = __shfl_sync(0xffffffffu, act, bsel + 12);

        c = fmaf(fv, c, iv * gv);
        float e = __expf(-2.f * fabsf(c));
        float h = ov * copysignf(__fdividef(1.f - e, 1.f + e), c);

        float* hnext = &g_hbuf[dir][(step + 1) & 1][0];
        if (l == 0)  __stcg(&hnext[uA], h);
        if (l == 16) __stcg(&hnext[uB], h);
        __syncthreads();                        // all warps done (stores issued, sH consumed)
        if (tid == 0) st_release_u32(&g_flag[dir][cb][0], (unsigned)(step + 2));
        // history store off the critical path (consumed only by fc_mma after kernel end)
        if (l == 0)  hs[(size_t)step*H_DIM + uA] = h;
        if (l == 16) hs[(size_t)step*H_DIM + uB] = h;
    }
}

// ---------------- phase 3: out = concat(h_fwd, h_bwd) @ fc_W^T + fc_b via TF32 MMA ----------------
__global__ __launch_bounds__(256, 1) void fc_mma(
    const float* __restrict__ fcW, const float* __restrict__ fcb,
    float* __restrict__ out)
{
    __shared__ float sA[128 * 32];
    __shared__ float sB[128 * 32];

    const int tid = threadIdx.x;
    const int warp = tid >> 5, l = tid & 31;
    const int wm = warp >> 1, wn = warp & 1;
    const int g = l >> 2, t = l & 3;
    const int m0 = blockIdx.y * 128, n0 = blockIdx.x * 128;

    const int sr  = tid >> 3;
    const int sc4 = tid & 7;
    const int scs = ((sc4 ^ (sr & 7)) << 2);

    float acc[2][8][4];
    #pragma unroll
    for (int mi = 0; mi < 2; ++mi)
        #pragma unroll
        for (int ni = 0; ni < 8; ++ni)
            #pragma unroll
            for (int e = 0; e < 4; ++e) acc[mi][ni][e] = 0.f;

    float4 pa[4], pb[4];
    {
        const int kc = sc4 * 4;
        #pragma unroll
        for (int p = 0; p < 4; ++p) {
            int m = m0 + sr + 32 * p;
            const float* asrc = (kc < H_DIM) ? &g_hs[0][m][kc]
                                             : &g_hs[1][T_LEN - 1 - m][kc - H_DIM];
            pa[p] = *(const float4*)asrc;
            int n = n0 + sr + 32 * p;
            pb[p] = (n < C_DIM) ? *(const float4*)(fcW + (size_t)n * (2 * H_DIM) + kc)
                                : make_float4(0.f, 0.f, 0.f, 0.f);
        }
        #pragma unroll
        for (int p = 0; p < 4; ++p) {
            int r = sr + 32 * p;
            float* da = &sA[r * 32 + scs];
            float* db = &sB[r * 32 + scs];
            da[0] = to_tf32(pa[p].x); da[1] = to_tf32(pa[p].y); da[2] = to_tf32(pa[p].z); da[3] = to_tf32(pa[p].w);
            db[0] = to_tf32(pb[p].x); db[1] = to_tf32(pb[p].y); db[2] = to_tf32(pb[p].z); db[3] = to_tf32(pb[p].w);
        }
    }
    __syncthreads();

    const int KTOT = 2 * H_DIM;
    for (int kt = 0; kt < KTOT / 32; ++kt) {
        if (kt < KTOT / 32 - 1) {
            const int kc = (kt + 1) * 32 + sc4 * 4;
            #pragma unroll
            for (int p = 0; p < 4; ++p) {
                int m = m0 + sr + 32 * p;
                const float* asrc = (kc < H_DIM) ? &g_hs[0][m][kc]
                                                 : &g_hs[1][T_LEN - 1 - m][kc - H_DIM];
                pa[p] = *(const float4*)asrc;
                int n = n0 + sr + 32 * p;
                pb[p] = (n < C_DIM) ? *(const float4*)(fcW + (size_t)n * (2 * H_DIM) + kc)
                                    : make_float4(0.f, 0.f, 0.f, 0.f);
            }
        }
        #pragma unroll
        for (int k8 = 0; k8 < 4; ++k8) {
            const int kk = k8 * 8;
            uint32_t a[2][4], b[8][2];
            #pragma unroll
            for (int mi = 0; mi < 2; ++mi) {
                int r = wm * 32 + mi * 16 + g;
                a[mi][0] = __float_as_uint(sA[swz(r,     kk + t)]);
                a[mi][1] = __float_as_uint(sA[swz(r + 8, kk + t)]);
                a[mi][2] = __float_as_uint(sA[swz(r,     kk + t + 4)]);
                a[mi][3] = __float_as_uint(sA[swz(r + 8, kk + t + 4)]);
            }
            #pragma unroll
            for (int ni = 0; ni < 8; ++ni) {
                int rn = wn * 64 + ni * 8 + g;
                b[ni][0] = __float_as_uint(sB[swz(rn, kk + t)]);
                b[ni][1] = __float_as_uint(sB[swz(rn, kk + t + 4)]);
            }
            #pragma unroll
            for (int mi = 0; mi < 2; ++mi)
                #pragma unroll
                for (int ni = 0; ni < 8; ++ni)
                    mma_tf32(acc[mi][ni], a[mi], b[ni]);
        }
        __syncthreads();
        if (kt < KTOT / 32 - 1) {
            #pragma unroll
            for (int p = 0; p < 4; ++p) {
                int r = sr + 32 * p;
                float* da = &sA[r * 32 + scs];
                float* db = &sB[r * 32 + scs];
                da[0] = to_tf32(pa[p].x); da[1] = to_tf32(pa[p].y); da[2] = to_tf32(pa[p].z); da[3] = to_tf32(pa[p].w);
                db[0] = to_tf32(pb[p].x); db[1] = to_tf32(pb[p].y); db[2] = to_tf32(pb[p].z); db[3] = to_tf32(pb[p].w);
            }
            __syncthreads();
        }
    }

    #pragma unroll
    for (int mi = 0; mi < 2; ++mi) {
        int r0 = m0 + wm * 32 + mi * 16 + g;
        #pragma unroll
        for (int ni = 0; ni < 8; ++ni) {
            int n = n0 + wn * 64 + ni * 8 + 2 * t;
            if (n < C_DIM) {
                float bb0 = __ldg(fcb + n);
                float bb1 = __ldg(fcb + n + 1);
                float2 v0 = make_float2(acc[mi][ni][0] + bb0, acc[mi][ni][1] + bb1);
                float2 v1 = make_float2(acc[mi][ni][2] + bb0, acc[mi][ni][3] + bb1);
                *(float2*)&out[(size_t)r0 * C_DIM + n]       = v0;
                *(float2*)&out[(size_t)(r0 + 8) * C_DIM + n] = v1;
            }
        }
    }
}

// ---------------- launch ----------------
extern "C" void kernel_launch(void* const* d_in, const int* in_sizes, int n_in,
                              void* d_out, int out_size)
{
    const float* x      = (const float*)d_in[0];
    const float* W_ih_f = (const float*)d_in[1];
    const float* W_hh_f = (const float*)d_in[2];
    const float* b_ih_f = (const float*)d_in[3];
    const float* b_hh_f = (const float*)d_in[4];
    const float* W_ih_b = (const float*)d_in[5];
    const float* W_hh_b = (const float*)d_in[6];
    const float* b_ih_b = (const float*)d_in[7];
    const float* b_hh_b = (const float*)d_in[8];
    const float* fc_W   = (const float*)d_in[9];
    const float* fc_b   = (const float*)d_in[10];
    float* out = (float*)d_out;

    cudaFuncSetAttribute(scan_kernel, cudaFuncAttributeMaxDynamicSharedMemorySize, SCAN_SMEM);

    init_kernel<<<32, 256>>>();
    xproj_mma<<<dim3(FH/128, T_LEN/128, 2), 256>>>(x, W_ih_f, W_ih_b,
                                                   b_ih_f, b_hh_f, b_ih_b, b_hh_b);
    scan_kernel<<<2*NCTA_DIR, 256, SCAN_SMEM>>>(W_hh_f, W_hh_b);
    fc_mma<<<dim3(8, T_LEN/128), 256>>>(fc_W, fc_b, out);
}

// round 17
// speedup vs baseline: 1.0882x; 1.0882x over previous
#include <cuda_runtime.h>
#include <math.h>
#include <stdint.h>

#define T_LEN  2048
#define IN_DIM 1024
#define H_DIM  1024
#define FH     4096
#define C_DIM  1000
#define NCTA_DIR 64
#define SCAN_SMEM ((16*1024 + 1024) * 4)

// ---------------- device scratch (no allocations allowed) ----------------
__device__ __align__(16) float g_xp[2][T_LEN][FH];      // input projections (fwd, bwd-reversed order)
__device__ __align__(16) float g_hs[2][T_LEN][H_DIM];   // all hidden states (bwd stored in reversed time)
__device__ __align__(16) float g_hbuf[2][2][H_DIM];     // double-buffered h per direction
// per-CTA progress flags, padded to 256B so consecutive flags land on distinct LTS slices
__device__ __align__(256) unsigned g_flag[2][NCTA_DIR][64];

__device__ __forceinline__ void st_release_u32(unsigned* p, unsigned v) {
    asm volatile("st.release.gpu.global.u32 [%0],%1;" :: "l"(p), "r"(v) : "memory");
}
__device__ __forceinline__ unsigned ld_acquire_u32(const unsigned* p) {
    unsigned v;
    asm volatile("ld.acquire.gpu.global.u32 %0,[%1];" : "=r"(v) : "l"(p) : "memory");
    return v;
}

// packed dual-FMA: one instruction, two exact fp32 FMAs (sm_103a FFMA2)
__device__ __forceinline__ void fma2(unsigned long long& acc,
                                     unsigned long long a, unsigned long long b) {
    asm("fma.rn.f32x2 %0, %1, %2, %0;" : "+l"(acc) : "l"(a), "l"(b));
}
__device__ __forceinline__ float f32x2_sum(unsigned long long p) {
    unsigned lo, hi;
    asm("mov.b64 {%0,%1}, %2;" : "=r"(lo), "=r"(hi) : "l"(p));
    return __uint_as_float(lo) + __uint_as_float(hi);
}

__device__ __forceinline__ float to_tf32(float x) {
    uint32_t u;
    asm("cvt.rna.tf32.f32 %0, %1;" : "=r"(u) : "f"(x));
    return __uint_as_float(u);
}

__device__ __forceinline__ void mma_tf32(float* c, const uint32_t* a, const uint32_t* b) {
    asm volatile(
        "mma.sync.aligned.m16n8k8.row.col.f32.tf32.tf32.f32 "
        "{%0,%1,%2,%3}, {%4,%5,%6,%7}, {%8,%9}, {%0,%1,%2,%3};\n"
        : "+f"(c[0]), "+f"(c[1]), "+f"(c[2]), "+f"(c[3])
        : "r"(a[0]), "r"(a[1]), "r"(a[2]), "r"(a[3]), "r"(b[0]), "r"(b[1]));
}

__device__ __forceinline__ int swz(int r, int c) {
    return r * 32 + ((((c >> 2) ^ (r & 7)) << 2) | (c & 3));
}

// ---------------- init: reset flags + h0 every launch/replay ----------------
__global__ void init_kernel() {
    int tid = blockIdx.x * blockDim.x + threadIdx.x;
    if (tid < 2 * 2 * H_DIM) ((float*)g_hbuf)[tid] = 0.f;
    if (tid < 2 * NCTA_DIR * 64) ((unsigned*)g_flag)[tid] = 1u;   // h[0] ready
}

// ---------------- phase 1: x @ W_ih^T + b_ih + b_hh via TF32 tensor cores ----------------
__global__ __launch_bounds__(256, 1) void xproj_mma(
    const float* __restrict__ x,
    const float* __restrict__ Wf, const float* __restrict__ Wb,
    const float* __restrict__ bif, const float* __restrict__ bhf,
    const float* __restrict__ bib, const float* __restrict__ bhb)
{
    const int dir = blockIdx.z;
    const float* __restrict__ W  = dir ? Wb  : Wf;
    const float* __restrict__ b1 = dir ? bib : bif;
    const float* __restrict__ b2 = dir ? bhb : bhf;

    __shared__ float sA[128 * 32];
    __shared__ float sB[128 * 32];

    const int tid = threadIdx.x;
    const int warp = tid >> 5, l = tid & 31;
    const int wm = warp >> 1, wn = warp & 1;
    const int g = l >> 2, t = l & 3;
    const int m0 = blockIdx.y * 128, n0 = blockIdx.x * 128;

    const int sr  = tid >> 3;
    const int sc4 = tid & 7;
    const int scs = ((sc4 ^ (sr & 7)) << 2);

    float acc[2][8][4];
    #pragma unroll
    for (int mi = 0; mi < 2; ++mi)
        #pragma unroll
        for (int ni = 0; ni < 8; ++ni)
            #pragma unroll
            for (int e = 0; e < 4; ++e) acc[mi][ni][e] = 0.f;

    float4 pa[4], pb[4];
    {
        const int kc = sc4 * 4;
        #pragma unroll
        for (int p = 0; p < 4; ++p) {
            int m = m0 + sr + 32 * p;
            int ar = dir ? (T_LEN - 1 - m) : m;
            pa[p] = *(const float4*)(x + (size_t)ar * IN_DIM + kc);
            pb[p] = *(const float4*)(W + (size_t)(n0 + sr + 32 * p) * IN_DIM + kc);
        }
        #pragma unroll
        for (int p = 0; p < 4; ++p) {
            int r = sr + 32 * p;
            float* da = &sA[r * 32 + scs];
            float* db = &sB[r * 32 + scs];
            da[0] = to_tf32(pa[p].x); da[1] = to_tf32(pa[p].y); da[2] = to_tf32(pa[p].z); da[3] = to_tf32(pa[p].w);
            db[0] = to_tf32(pb[p].x); db[1] = to_tf32(pb[p].y); db[2] = to_tf32(pb[p].z); db[3] = to_tf32(pb[p].w);
        }
    }
    __syncthreads();

    for (int kt = 0; kt < IN_DIM / 32; ++kt) {
        if (kt < IN_DIM / 32 - 1) {
            const int kc = (kt + 1) * 32 + sc4 * 4;
            #pragma unroll
            for (int p = 0; p < 4; ++p) {
                int m = m0 + sr + 32 * p;
                int ar = dir ? (T_LEN - 1 - m) : m;
                pa[p] = *(const float4*)(x + (size_t)ar * IN_DIM + kc);
                pb[p] = *(const float4*)(W + (size_t)(n0 + sr + 32 * p) * IN_DIM + kc);
            }
        }
        #pragma unroll
        for (int k8 = 0; k8 < 4; ++k8) {
            const int kk = k8 * 8;
            uint32_t a[2][4], b[8][2];
            #pragma unroll
            for (int mi = 0; mi < 2; ++mi) {
                int r = wm * 32 + mi * 16 + g;
                a[mi][0] = __float_as_uint(sA[swz(r,     kk + t)]);
                a[mi][1] = __float_as_uint(sA[swz(r + 8, kk + t)]);
                a[mi][2] = __float_as_uint(sA[swz(r,     kk + t + 4)]);
                a[mi][3] = __float_as_uint(sA[swz(r + 8, kk + t + 4)]);
            }
            #pragma unroll
            for (int ni = 0; ni < 8; ++ni) {
                int rn = wn * 64 + ni * 8 + g;
                b[ni][0] = __float_as_uint(sB[swz(rn, kk + t)]);
                b[ni][1] = __float_as_uint(sB[swz(rn, kk + t + 4)]);
            }
            #pragma unroll
            for (int mi = 0; mi < 2; ++mi)
                #pragma unroll
                for (int ni = 0; ni < 8; ++ni)
                    mma_tf32(acc[mi][ni], a[mi], b[ni]);
        }
        __syncthreads();
        if (kt < IN_DIM / 32 - 1) {
            #pragma unroll
            for (int p = 0; p < 4; ++p) {
                int r = sr + 32 * p;
                float* da = &sA[r * 32 + scs];
                float* db = &sB[r * 32 + scs];
                da[0] = to_tf32(pa[p].x); da[1] = to_tf32(pa[p].y); da[2] = to_tf32(pa[p].z); da[3] = to_tf32(pa[p].w);
                db[0] = to_tf32(pb[p].x); db[1] = to_tf32(pb[p].y); db[2] = to_tf32(pb[p].z); db[3] = to_tf32(pb[p].w);
            }
            __syncthreads();
        }
    }

    #pragma unroll
    for (int mi = 0; mi < 2; ++mi) {
        int r0 = m0 + wm * 32 + mi * 16 + g;
        #pragma unroll
        for (int ni = 0; ni < 8; ++ni) {
            int n = n0 + wn * 64 + ni * 8 + 2 * t;
            float bb0 = __ldg(b1 + n)     + __ldg(b2 + n);
            float bb1 = __ldg(b1 + n + 1) + __ldg(b2 + n + 1);
            float2 v0 = make_float2(acc[mi][ni][0] + bb0, acc[mi][ni][1] + bb1);
            float2 v1 = make_float2(acc[mi][ni][2] + bb0, acc[mi][ni][3] + bb1);
            *(float2*)&g_xp[dir][r0][n]     = v0;
            *(float2*)&g_xp[dir][r0 + 8][n] = v1;
        }
    }
}

// ---------------- phase 2: persistent LSTM scan (R14 + fused poll/fetch + xpv prefetch) ----------------
// 128 CTAs (blockIdx>>6 = direction, &63 = chunk). 256 threads = 8 warps, 2 units/warp.
// Unit A: all 4 gates in regs. Unit B: gates 0,1 regs; gates 2,3 smem. FFMA2 GEMV.
// Handoff: FUSED acquire-flag poll + __ldcg h fetch in the same loop iteration (data in
// flight when detection passes, validly ordered), per-CTA release flag. xp element for
// step t+1 is prefetched right after staging so its latency hides under the full GEMV.
__global__ __launch_bounds__(256, 1) void scan_kernel(
    const float* __restrict__ Whh_f, const float* __restrict__ Whh_b)
{
    extern __shared__ float smem[];
    float* sW = smem;             // 16 rows x 1024: unit B gates {2,3}
    float* sH = smem + 16*1024;   // 1024 (staged h)

    const int dir = blockIdx.x >> 6;
    const int cb  = blockIdx.x & 63;
    const float* __restrict__ Whh = dir ? Whh_b : Whh_f;

    const int tid = threadIdx.x;
    const int w = tid >> 5;
    const int l = tid & 31;
    const int uA = cb*16 + w;        // register unit (all 4 gates)
    const int uB = cb*16 + 8 + w;    // mixed unit (gates 0,1 regs; 2,3 smem)

    // cooperative load of smem weights: unit B gates {2,3}, 16 rows
    for (int i = tid; i < 16 * 256; i += 256) {
        int rr   = i >> 8;        // 0..15
        int col4 = i & 255;
        int lw   = rr >> 1;
        int gate = 2 + (rr & 1);
        int uu   = cb*16 + 8 + lw;
        ((float4*)sW)[i] = __ldg((const float4*)(Whh + (size_t)(gate*H_DIM + uu)*H_DIM) + col4);
    }

    // register weights as packed f32x2 pairs: unit A gates 0..3, unit B gates 0..1
    ulonglong2 wrA[4][8];
    #pragma unroll
    for (int g = 0; g < 4; ++g) {
        const ulonglong2* base = (const ulonglong2*)(Whh + (size_t)(g*H_DIM + uA)*H_DIM);
        #pragma unroll
        for (int jj = 0; jj < 8; ++jj)
            wrA[g][jj] = __ldg(base + (l + 32*jj));
    }
    ulonglong2 wrB[2][8];
    #pragma unroll
    for (int g = 0; g < 2; ++g) {
        const ulonglong2* base = (const ulonglong2*)(Whh + (size_t)(g*H_DIM + uB)*H_DIM);
        #pragma unroll
        for (int jj = 0; jj < 8; ++jj)
            wrB[g][jj] = __ldg(base + (l + 32*jj));
    }
    __syncthreads();

    float c = 0.f;                               // lanes<16: cA; lanes>=16: cB
    const float* xp = &g_xp[dir][0][0];
    float* hs = &g_hs[dir][0][0];
    // lanes in a quad share one xp element: gate=(l>>2)&3, unit A for l<16 else B
    const int xrow = (((l >> 2) & 3))*H_DIM + ((l & 16) ? uB : uA);
    const unsigned* myflag = &g_flag[dir][tid >> 2][0];
    const int bsel = l & 16;                     // shfl source base: 0 (unit A) / 16 (unit B)

    // prefetch xp for step 0
    float xpv = __ldg(xp + xrow);

    for (int step = 0; step < T_LEN; ++step) {
        // fused poll + h fetch (R6-proven): the ldcg issued in the iteration where the
        // acquire passes is properly ordered and already in flight at detection time.
        const unsigned expect = (unsigned)(step + 1);
        const float4* hp = (const float4*)&g_hbuf[dir][step & 1][0] + tid;
        float4 hv;
        for (;;) {
            unsigned f = ld_acquire_u32(myflag);
            hv = __ldcg(hp);
            if (__all_sync(0xffffffffu, f >= expect)) break;
        }
        ((float4*)sH)[tid] = hv;

        // prefetch next step's xp element (consumed ~1 full GEMV+tail later)
        float xpv_next = 0.f;
        if (step + 1 < T_LEN) xpv_next = __ldg(xp + (size_t)(step + 1)*FH + xrow);
        __syncthreads();

        unsigned long long acc2[8];
        #pragma unroll
        for (int g = 0; g < 8; ++g) acc2[g] = 0ull;   // packed {0.f, 0.f}

        const ulonglong2* sH2 = (const ulonglong2*)sH;
        const ulonglong2* sW2 = (const ulonglong2*)sW;
        const ulonglong2* r6 = sW2 + (w*2 + 0)*256;   // unit B gate 2
        const ulonglong2* r7 = sW2 + (w*2 + 1)*256;   // unit B gate 3
        #pragma unroll
        for (int jj = 0; jj < 8; ++jj) {
            ulonglong2 hq = sH2[l + 32*jj];
            #pragma unroll
            for (int g = 0; g < 4; ++g) {
                fma2(acc2[g], wrA[g][jj].x, hq.x);
                fma2(acc2[g], wrA[g][jj].y, hq.y);
            }
            fma2(acc2[4], wrB[0][jj].x, hq.x);
            fma2(acc2[4], wrB[0][jj].y, hq.y);
            fma2(acc2[5], wrB[1][jj].x, hq.x);
            fma2(acc2[5], wrB[1][jj].y, hq.y);
            ulonglong2 q2 = r6[l + 32*jj];
            ulonglong2 q3 = r7[l + 32*jj];
            fma2(acc2[6], q2.x, hq.x);
            fma2(acc2[6], q2.y, hq.y);
            fma2(acc2[7], q3.x, hq.x);
            fma2(acc2[7], q3.y, hq.y);
        }
        float acc[8];
        #pragma unroll
        for (int g = 0; g < 8; ++g) acc[g] = f32x2_sum(acc2[g]);

        // value-merging butterfly: 16 shfls
        #pragma unroll
        for (int g = 0; g < 8; ++g) acc[g] += __shfl_xor_sync(0xffffffffu, acc[g], 16);
        float v0 = (l & 16) ? acc[4] : acc[0];
        float v1 = (l & 16) ? acc[5] : acc[1];
        float v2 = (l & 16) ? acc[6] : acc[2];
        float v3 = (l & 16) ? acc[7] : acc[3];
        v0 += __shfl_xor_sync(0xffffffffu, v0, 8);
        v1 += __shfl_xor_sync(0xffffffffu, v1, 8);
        v2 += __shfl_xor_sync(0xffffffffu, v2, 8);
        v3 += __shfl_xor_sync(0xffffffffu, v3, 8);
        float u0 = (l & 8) ? v2 : v0;
        float u1 = (l & 8) ? v3 : v1;
        u0 += __shfl_xor_sync(0xffffffffu, u0, 4);
        u1 += __shfl_xor_sync(0xffffffffu, u1, 4);
        float t = (l & 4) ? u1 : u0;
        t += __shfl_xor_sync(0xffffffffu, t, 2);
        t += __shfl_xor_sync(0xffffffffu, t, 1);
        // lane l holds gate sum for g(l) = 4*(l>>4) + ((l>>2)&3)

        float pre = t + xpv;
        float act;
        if (((l >> 2) & 3) == 2) {             // candidate gate: tanh
            float e = __expf(-2.f * fabsf(pre));
            act = copysignf(__fdividef(1.f - e, 1.f + e), pre);
        } else {                               // i/f/o gates: sigmoid
            act = __fdividef(1.f, 1.f + __expf(-pre));
        }

        // 4 broadcasts: lanes<16 gather unit A's gates, lanes>=16 unit B's
        float iv = __shfl_sync(0xffffffffu, act, bsel + 0);
        float fv = __shfl_sync(0xffffffffu, act, bsel + 4);
        float gv = __shfl_sync(0xffffffffu, act, bsel + 8);
        float ov = __shfl_sync(0xffffffffu, act, bsel + 12);

        c = fmaf(fv, c, iv * gv);
        float e = __expf(-2.f * fabsf(c));
        float h = ov * copysignf(__fdividef(1.f - e, 1.f + e), c);

        float* hnext = &g_hbuf[dir][(step + 1) & 1][0];
        if (l == 0)  __stcg(&hnext[uA], h);
        if (l == 16) __stcg(&hnext[uB], h);
        __syncthreads();                        // all warps' h stores issued before release
        if (tid == 0) st_release_u32(&g_flag[dir][cb][0], (unsigned)(step + 2));
        // history store off the critical path (consumed only by fc_mma after kernel end)
        if (l == 0)  hs[(size_t)step*H_DIM + uA] = h;
        if (l == 16) hs[(size_t)step*H_DIM + uB] = h;

        xpv = xpv_next;
    }
}

// ---------------- phase 3: out = concat(h_fwd, h_bwd) @ fc_W^T + fc_b via TF32 MMA ----------------
__global__ __launch_bounds__(256, 1) void fc_mma(
    const float* __restrict__ fcW, const float* __restrict__ fcb,
    float* __restrict__ out)
{
    __shared__ float sA[128 * 32];
    __shared__ float sB[128 * 32];

    const int tid = threadIdx.x;
    const int warp = tid >> 5, l = tid & 31;
    const int wm = warp >> 1, wn = warp & 1;
    const int g = l >> 2, t = l & 3;
    const int m0 = blockIdx.y * 128, n0 = blockIdx.x * 128;

    const int sr  = tid >> 3;
    const int sc4 = tid & 7;
    const int scs = ((sc4 ^ (sr & 7)) << 2);

    float acc[2][8][4];
    #pragma unroll
    for (int mi = 0; mi < 2; ++mi)
        #pragma unroll
        for (int ni = 0; ni < 8; ++ni)
            #pragma unroll
            for (int e = 0; e < 4; ++e) acc[mi][ni][e] = 0.f;

    float4 pa[4], pb[4];
    {
        const int kc = sc4 * 4;
        #pragma unroll
        for (int p = 0; p < 4; ++p) {
            int m = m0 + sr + 32 * p;
            const float* asrc = (kc < H_DIM) ? &g_hs[0][m][kc]
                                             : &g_hs[1][T_LEN - 1 - m][kc - H_DIM];
            pa[p] = *(const float4*)asrc;
            int n = n0 + sr + 32 * p;
            pb[p] = (n < C_DIM) ? *(const float4*)(fcW + (size_t)n * (2 * H_DIM) + kc)
                                : make_float4(0.f, 0.f, 0.f, 0.f);
        }
        #pragma unroll
        for (int p = 0; p < 4; ++p) {
            int r = sr + 32 * p;
            float* da = &sA[r * 32 + scs];
            float* db = &sB[r * 32 + scs];
            da[0] = to_tf32(pa[p].x); da[1] = to_tf32(pa[p].y); da[2] = to_tf32(pa[p].z); da[3] = to_tf32(pa[p].w);
            db[0] = to_tf32(pb[p].x); db[1] = to_tf32(pb[p].y); db[2] = to_tf32(pb[p].z); db[3] = to_tf32(pb[p].w);
        }
    }
    __syncthreads();

    const int KTOT = 2 * H_DIM;
    for (int kt = 0; kt < KTOT / 32; ++kt) {
        if (kt < KTOT / 32 - 1) {
            const int kc = (kt + 1) * 32 + sc4 * 4;
            #pragma unroll
            for (int p = 0; p < 4; ++p) {
                int m = m0 + sr + 32 * p;
                const float* asrc = (kc < H_DIM) ? &g_hs[0][m][kc]
                                                 : &g_hs[1][T_LEN - 1 - m][kc - H_DIM];
                pa[p] = *(const float4*)asrc;
                int n = n0 + sr + 32 * p;
                pb[p] = (n < C_DIM) ? *(const float4*)(fcW + (size_t)n * (2 * H_DIM) + kc)
                                    : make_float4(0.f, 0.f, 0.f, 0.f);
            }
        }
        #pragma unroll
        for (int k8 = 0; k8 < 4; ++k8) {
            const int kk = k8 * 8;
            uint32_t a[2][4], b[8][2];
            #pragma unroll
            for (int mi = 0; mi < 2; ++mi) {
                int r = wm * 32 + mi * 16 + g;
                a[mi][0] = __float_as_uint(sA[swz(r,     kk + t)]);
                a[mi][1] = __float_as_uint(sA[swz(r + 8, kk + t)]);
                a[mi][2] = __float_as_uint(sA[swz(r,     kk + t + 4)]);
                a[mi][3] = __float_as_uint(sA[swz(r + 8, kk + t + 4)]);
            }
            #pragma unroll
            for (int ni = 0; ni < 8; ++ni) {
                int rn = wn * 64 + ni * 8 + g;
                b[ni][0] = __float_as_uint(sB[swz(rn, kk + t)]);
                b[ni][1] = __float_as_uint(sB[swz(rn, kk + t + 4)]);
            }
            #pragma unroll
            for (int mi = 0; mi < 2; ++mi)
                #pragma unroll
                for (int ni = 0; ni < 8; ++ni)
                    mma_tf32(acc[mi][ni], a[mi], b[ni]);
        }
        __syncthreads();
        if (kt < KTOT / 32 - 1) {
            #pragma unroll
            for (int p = 0; p < 4; ++p) {
                int r = sr + 32 * p;
                float* da = &sA[r * 32 + scs];
                float* db = &sB[r * 32 + scs];
                da[0] = to_tf32(pa[p].x); da[1] = to_tf32(pa[p].y); da[2] = to_tf32(pa[p].z); da[3] = to_tf32(pa[p].w);
                db[0] = to_tf32(pb[p].x); db[1] = to_tf32(pb[p].y); db[2] = to_tf32(pb[p].z); db[3] = to_tf32(pb[p].w);
            }
            __syncthreads();
        }
    }

    #pragma unroll
    for (int mi = 0; mi < 2; ++mi) {
        int r0 = m0 + wm * 32 + mi * 16 + g;
        #pragma unroll
        for (int ni = 0; ni < 8; ++ni) {
            int n = n0 + wn * 64 + ni * 8 + 2 * t;
            if (n < C_DIM) {
                float bb0 = __ldg(fcb + n);
                float bb1 = __ldg(fcb + n + 1);
                float2 v0 = make_float2(acc[mi][ni][0] + bb0, acc[mi][ni][1] + bb1);
                float2 v1 = make_float2(acc[mi][ni][2] + bb0, acc[mi][ni][3] + bb1);
                *(float2*)&out[(size_t)r0 * C_DIM + n]       = v0;
                *(float2*)&out[(size_t)(r0 + 8) * C_DIM + n] = v1;
            }
        }
    }
}

// ---------------- launch ----------------
extern "C" void kernel_launch(void* const* d_in, const int* in_sizes, int n_in,
                              void* d_out, int out_size)
{
    const float* x      = (const float*)d_in[0];
    const float* W_ih_f = (const float*)d_in[1];
    const float* W_hh_f = (const float*)d_in[2];
    const float* b_ih_f = (const float*)d_in[3];
    const float* b_hh_f = (const float*)d_in[4];
    const float* W_ih_b = (const float*)d_in[5];
    const float* W_hh_b = (const float*)d_in[6];
    const float* b_ih_b = (const float*)d_in[7];
    const float* b_hh_b = (const float*)d_in[8];
    const float* fc_W   = (const float*)d_in[9];
    const float* fc_b   = (const float*)d_in[10];
    float* out = (float*)d_out;

    cudaFuncSetAttribute(scan_kernel, cudaFuncAttributeMaxDynamicSharedMemorySize, SCAN_SMEM);

    init_kernel<<<32, 256>>>();
    xproj_mma<<<dim3(FH/128, T_LEN/128, 2), 256>>>(x, W_ih_f, W_ih_b,
                                                   b_ih_f, b_hh_f, b_ih_b, b_hh_b);
    scan_kernel<<<2*NCTA_DIR, 256, SCAN_SMEM>>>(W_hh_f, W_hh_b);
    fc_mma<<<dim3(8, T_LEN/128), 256>>>(fc_W, fc_b, out);
}